// round 12
// baseline (speedup 1.0000x reference)
#include <cuda_runtime.h>

// Problem constants (fixed by setup_inputs)
constexpr int B = 4, H = 1024, W = 1024;
constexpr int TX = 32;          // output tile width
constexpr int TY = 16;          // output tile height (2 rows per thread)
constexpr int HX = TX + 10;     // 42: halo tile width
constexpr int HY = TY + 10;     // 26: halo tile height

__device__ __forceinline__ float rcpa(float x) {
    float r; asm("rcp.approx.f32 %0,%1;" : "=f"(r) : "f"(x)); return r;
}

// Disk rows (dy = -5..5): column start and width of the in-mask span, in
// kernel-column coords c = dx+5 (0..10). Row widths 5,7,9,11,11,11,11,11,9,7,5.
__device__ constexpr int ST[11] = {3, 2, 1, 0, 0, 0, 0, 0, 1, 2, 3};
__device__ constexpr int WD[11] = {5, 7, 9, 11, 11, 11, 11, 11, 9, 7, 5};

#define MK 1e30f
// QD[dy+5][dx+5] = dist - 0.5 (entries outside the disk are never evaluated).
__device__ constexpr float QD[11][11] = {
  {MK,MK,MK,4.885164807f,4.599019514f,4.5f,4.599019514f,4.885164807f,MK,MK,MK},
  {MK,MK,4.5f,3.972135955f,3.623105626f,3.5f,3.623105626f,3.972135955f,4.5f,MK,MK},
  {MK,4.5f,3.742640687f,3.105551276f,2.662277660f,2.5f,2.662277660f,3.105551276f,3.742640687f,4.5f,MK},
  {4.885164807f,3.972135955f,3.105551276f,2.328427125f,1.736067977f,1.5f,1.736067977f,2.328427125f,3.105551276f,3.972135955f,4.885164807f},
  {4.599019514f,3.623105626f,2.662277660f,1.736067977f,0.914213562f,0.5f,0.914213562f,1.736067977f,2.662277660f,3.623105626f,4.599019514f},
  {4.5f,3.5f,2.5f,1.5f,0.5f,-0.5f,0.5f,1.5f,2.5f,3.5f,4.5f},
  {4.599019514f,3.623105626f,2.662277660f,1.736067977f,0.914213562f,0.5f,0.914213562f,1.736067977f,2.662277660f,3.623105626f,4.599019514f},
  {4.885164807f,3.972135955f,3.105551276f,2.328427125f,1.736067977f,1.5f,1.736067977f,2.328427125f,3.105551276f,3.972135955f,4.885164807f},
  {MK,4.5f,3.742640687f,3.105551276f,2.662277660f,2.5f,2.662277660f,3.105551276f,3.742640687f,4.5f,MK},
  {MK,MK,4.5f,3.972135955f,3.623105626f,3.5f,3.623105626f,3.972135955f,4.5f,MK,MK},
  {MK,MK,MK,4.885164807f,4.599019514f,4.5f,4.599019514f,4.885164807f,MK,MK,MK}
};

__global__ __launch_bounds__(256)
void scatter_render_kernel(const float* __restrict__ x,
                           const float* __restrict__ lens,
                           float* __restrict__ out)
{
    __shared__ float2 s_ec[HY][HX];   // (inv_es = exp(-4*disp), coc)
    __shared__ float2 s_rg[HY][HX];   // (r, g)
    __shared__ float  s_b [HY][HX];   // b

    const int b   = blockIdx.z;
    const int gx0 = blockIdx.x * TX;
    const int gy0 = blockIdx.y * TY;

    const float scale = fabsf(lens[b]);
    const float* __restrict__ xb = x + (size_t)b * 4 * H * W;
    const float* __restrict__ pr = xb;
    const float* __restrict__ pg = xb + H * W;
    const float* __restrict__ pb = xb + 2 * H * W;
    const float* __restrict__ pd = xb + 3 * H * W;

    // ---- cooperative halo-tile fill (with edge clamp) ----
    const int tid = threadIdx.y * TX + threadIdx.x;
    for (int idx = tid; idx < HY * HX; idx += 256) {
        int yy = idx / HX;
        int xx = idx - yy * HX;
        int sy = gy0 + yy - 5; sy = min(max(sy, 0), H - 1);
        int sx = gx0 + xx - 5; sx = min(max(sx, 0), W - 1);
        int o  = sy * W + sx;
        float d  = pd[o];
        float ie = __expf(-4.0f * d);           // e^{-4 disp}
        float cc = scale * fabsf(d);
        s_ec[yy][xx] = make_float2(ie, cc);
        s_rg[yy][xx] = make_float2(pr[o], pg[o]);
        s_b [yy][xx] = pb[o];
    }
    __syncthreads();

    // ---- main gather: each thread owns 2 vertically adjacent outputs ----
    const int tx = threadIdx.x;
    const int ry = 2 * threadIdx.y;

    // ed = e^{+4 disp_dst} = rcp(inv_es at dst)
    const float ed0 = rcpa(s_ec[ry + 5][tx + 5].x);
    const float ed1 = rcpa(s_ec[ry + 6][tx + 5].x);

    float nr0 = 0.f, ng0 = 0.f, nb0 = 0.f, nd0 = 0.f;
    float nr1 = 0.f, ng1 = 0.f, nb1 = 0.f, nd1 = 0.f;

    // smem row ry+sr serves out0 as disk row sr (sr=0..10) and out1 as disk
    // row sr-1 (sr=1..11). Only columns inside either disk span are touched.
    #pragma unroll
    for (int sr = 0; sr < 12; ++sr) {
        #pragma unroll
        for (int sc = 0; sc < 11; ++sc) {
            const bool a0 = (sr <= 10) && (sc >= ST[sr])     && (sc < ST[sr]     + WD[sr]);
            const bool a1 = (sr >= 1)  && (sc >= ST[sr - 1]) && (sc < ST[sr - 1] + WD[sr - 1]);
            if (a0 || a1) {
                const float2 ec = s_ec[ry + sr][tx + sc];   // (inv_es, coc)
                const float2 rg = s_rg[ry + sr][tx + sc];
                const float  bb = s_b [ry + sr][tx + sc];
                if (a0) {
                    const float w  = __saturatef(ec.y - QD[sr][sc]);
                    const float oc = rcpa(fmaf(ed0, ec.x, 1.0f));   // sigmoid gate
                    const float wo = w * oc;
                    nr0 += wo * rg.x;  ng0 += wo * rg.y;  nb0 += wo * bb;  nd0 += wo;
                }
                if (a1) {
                    const float w  = __saturatef(ec.y - QD[sr - 1][sc]);
                    const float oc = rcpa(fmaf(ed1, ec.x, 1.0f));
                    const float wo = w * oc;
                    nr1 += wo * rg.x;  ng1 += wo * rg.y;  nb1 += wo * bb;  nd1 += wo;
                }
            }
        }
    }

    const int gx = gx0 + tx;
    const int gy = gy0 + ry;
    float* __restrict__ ob = out + (size_t)b * 3 * H * W;
    const float inv0 = __fdividef(1.0f, nd0 + 1e-8f);
    const float inv1 = __fdividef(1.0f, nd1 + 1e-8f);
    const int o0 = gy * W + gx;
    const int o1 = o0 + W;
    ob[o0]             = nr0 * inv0;
    ob[H * W + o0]     = ng0 * inv0;
    ob[2 * H * W + o0] = nb0 * inv0;
    ob[o1]             = nr1 * inv1;
    ob[H * W + o1]     = ng1 * inv1;
    ob[2 * H * W + o1] = nb1 * inv1;
}

extern "C" void kernel_launch(void* const* d_in, const int* in_sizes, int n_in,
                              void* d_out, int out_size)
{
    const float* x    = (const float*)d_in[0];
    const float* lens = (const float*)d_in[1];
    float* out        = (float*)d_out;

    dim3 block(TX, TY / 2, 1);              // 32 x 8 = 256 threads
    dim3 grid(W / TX, H / TY, B);           // 32 x 64 x 4
    scatter_render_kernel<<<grid, block>>>(x, lens, out);
}

// round 13
// speedup vs baseline: 1.2639x; 1.2639x over previous
#include <cuda_runtime.h>

// Problem constants (fixed by setup_inputs)
constexpr int B = 4, H = 1024, W = 1024;
constexpr int TX = 32;          // output tile width
constexpr int TY = 16;          // output tile height (2 rows per thread)
constexpr int HX = TX + 10;     // 42: halo tile width
constexpr int HY = TY + 10;     // 26: halo tile height

// Disk rows (dy = -5..5): column start and width of the in-mask span, in
// kernel-column coords c = dx+5 (0..10). Row widths 5,7,9,11,11,11,11,11,9,7,5.
__device__ constexpr int ST[11] = {3, 2, 1, 0, 0, 0, 0, 0, 1, 2, 3};
__device__ constexpr int WD[11] = {5, 7, 9, 11, 11, 11, 11, 11, 9, 7, 5};

#define MK 1e30f
// QD[dy+5][dx+5] = dist - 0.5 (entries outside the disk are never evaluated).
__device__ constexpr float QD[11][11] = {
  {MK,MK,MK,4.885164807f,4.599019514f,4.5f,4.599019514f,4.885164807f,MK,MK,MK},
  {MK,MK,4.5f,3.972135955f,3.623105626f,3.5f,3.623105626f,3.972135955f,4.5f,MK,MK},
  {MK,4.5f,3.742640687f,3.105551276f,2.662277660f,2.5f,2.662277660f,3.105551276f,3.742640687f,4.5f,MK},
  {4.885164807f,3.972135955f,3.105551276f,2.328427125f,1.736067977f,1.5f,1.736067977f,2.328427125f,3.105551276f,3.972135955f,4.885164807f},
  {4.599019514f,3.623105626f,2.662277660f,1.736067977f,0.914213562f,0.5f,0.914213562f,1.736067977f,2.662277660f,3.623105626f,4.599019514f},
  {4.5f,3.5f,2.5f,1.5f,0.5f,-0.5f,0.5f,1.5f,2.5f,3.5f,4.5f},
  {4.599019514f,3.623105626f,2.662277660f,1.736067977f,0.914213562f,0.5f,0.914213562f,1.736067977f,2.662277660f,3.623105626f,4.599019514f},
  {4.885164807f,3.972135955f,3.105551276f,2.328427125f,1.736067977f,1.5f,1.736067977f,2.328427125f,3.105551276f,3.972135955f,4.885164807f},
  {MK,4.5f,3.742640687f,3.105551276f,2.662277660f,2.5f,2.662277660f,3.105551276f,3.742640687f,4.5f,MK},
  {MK,MK,4.5f,3.972135955f,3.623105626f,3.5f,3.623105626f,3.972135955f,4.5f,MK,MK},
  {MK,MK,MK,4.885164807f,4.599019514f,4.5f,4.599019514f,4.885164807f,MK,MK,MK}
};

__global__ __launch_bounds__(256)
void scatter_render_kernel(const float* __restrict__ x,
                           const float* __restrict__ lens,
                           float* __restrict__ out)
{
    __shared__ float2 s_ec[HY][HX];   // (inv_es = exp(-4*disp), coc)
    __shared__ float2 s_rg[HY][HX];   // (r, g)
    __shared__ float  s_b [HY][HX];   // b

    const int b   = blockIdx.z;
    const int gx0 = blockIdx.x * TX;
    const int gy0 = blockIdx.y * TY;

    const float scale = fabsf(lens[b]);
    const float* __restrict__ xb = x + (size_t)b * 4 * H * W;
    const float* __restrict__ pr = xb;
    const float* __restrict__ pg = xb + H * W;
    const float* __restrict__ pb = xb + 2 * H * W;
    const float* __restrict__ pd = xb + 3 * H * W;

    // ---- cooperative halo-tile fill (with edge clamp) ----
    const int tid = threadIdx.y * TX + threadIdx.x;
    for (int idx = tid; idx < HY * HX; idx += 256) {
        int yy = idx / HX;
        int xx = idx - yy * HX;
        int sy = gy0 + yy - 5; sy = min(max(sy, 0), H - 1);
        int sx = gx0 + xx - 5; sx = min(max(sx, 0), W - 1);
        int o  = sy * W + sx;
        float d  = pd[o];
        float ie = __expf(-4.0f * d);           // e^{-4 disp}
        float cc = scale * fabsf(d);
        s_ec[yy][xx] = make_float2(ie, cc);
        s_rg[yy][xx] = make_float2(pr[o], pg[o]);
        s_b [yy][xx] = pb[o];
    }
    __syncthreads();

    // ---- main gather: each thread owns 2 vertically adjacent outputs ----
    const int tx = threadIdx.x;
    const int ry = 2 * threadIdx.y;

    // ed = e^{+4 disp_dst} = 1 / inv_es(dst)
    const float ed0 = __fdividef(1.0f, s_ec[ry + 5][tx + 5].x);
    const float ed1 = __fdividef(1.0f, s_ec[ry + 6][tx + 5].x);

    float nr0 = 0.f, ng0 = 0.f, nb0 = 0.f, nd0 = 0.f;
    float nr1 = 0.f, ng1 = 0.f, nb1 = 0.f, nd1 = 0.f;

    // smem row ry+sr serves out0 as disk row sr (sr=0..10) and out1 as disk
    // row sr-1 (sr=1..11). Only columns inside either disk span are touched.
    #pragma unroll
    for (int sr = 0; sr < 12; ++sr) {
        #pragma unroll
        for (int sc = 0; sc < 11; ++sc) {
            const bool a0 = (sr <= 10) && (sc >= ST[sr])     && (sc < ST[sr]     + WD[sr]);
            const bool a1 = (sr >= 1)  && (sc >= ST[sr - 1]) && (sc < ST[sr - 1] + WD[sr - 1]);
            if (a0 || a1) {
                const float2 ec = s_ec[ry + sr][tx + sc];   // (inv_es, coc)
                const float2 rg = s_rg[ry + sr][tx + sc];
                const float  bb = s_b [ry + sr][tx + sc];
                if (a0) {
                    const float w  = __saturatef(ec.y - QD[sr][sc]);
                    // w * sigmoid(4(ds - dd)) = w / (1 + ed*inv_es)
                    const float wo = __fdividef(w, fmaf(ed0, ec.x, 1.0f));
                    nr0 += wo * rg.x;  ng0 += wo * rg.y;  nb0 += wo * bb;  nd0 += wo;
                }
                if (a1) {
                    const float w  = __saturatef(ec.y - QD[sr - 1][sc]);
                    const float wo = __fdividef(w, fmaf(ed1, ec.x, 1.0f));
                    nr1 += wo * rg.x;  ng1 += wo * rg.y;  nb1 += wo * bb;  nd1 += wo;
                }
            }
        }
    }

    const int gx = gx0 + tx;
    const int gy = gy0 + ry;
    float* __restrict__ ob = out + (size_t)b * 3 * H * W;
    const float inv0 = __fdividef(1.0f, nd0 + 1e-8f);
    const float inv1 = __fdividef(1.0f, nd1 + 1e-8f);
    const int o0 = gy * W + gx;
    const int o1 = o0 + W;
    ob[o0]             = nr0 * inv0;
    ob[H * W + o0]     = ng0 * inv0;
    ob[2 * H * W + o0] = nb0 * inv0;
    ob[o1]             = nr1 * inv1;
    ob[H * W + o1]     = ng1 * inv1;
    ob[2 * H * W + o1] = nb1 * inv1;
}

extern "C" void kernel_launch(void* const* d_in, const int* in_sizes, int n_in,
                              void* d_out, int out_size)
{
    const float* x    = (const float*)d_in[0];
    const float* lens = (const float*)d_in[1];
    float* out        = (float*)d_out;

    dim3 block(TX, TY / 2, 1);              // 32 x 8 = 256 threads
    dim3 grid(W / TX, H / TY, B);           // 32 x 64 x 4
    scatter_render_kernel<<<grid, block>>>(x, lens, out);
}

// round 16
// speedup vs baseline: 1.3031x; 1.0310x over previous
#include <cuda_runtime.h>

// Problem constants (fixed by setup_inputs)
constexpr int B = 4, H = 1024, W = 1024;
constexpr int TX = 32;          // output tile width
constexpr int TY = 16;          // output tile height (2 rows per thread)
constexpr int HX = TX + 10;     // 42: halo tile width
constexpr int HY = TY + 10;     // 26: halo tile height

// Disk rows (dy = -5..5): column start and width of the in-mask span, in
// kernel-column coords c = dx+5 (0..10). Row widths 5,7,9,11,11,11,11,11,9,7,5.
__device__ constexpr int ST[11] = {3, 2, 1, 0, 0, 0, 0, 0, 1, 2, 3};
__device__ constexpr int WD[11] = {5, 7, 9, 11, 11, 11, 11, 11, 9, 7, 5};

#define MK 1e30f
// QD[dy+5][dx+5] = dist - 0.5 (entries outside the disk are never evaluated).
__device__ constexpr float QD[11][11] = {
  {MK,MK,MK,4.885164807f,4.599019514f,4.5f,4.599019514f,4.885164807f,MK,MK,MK},
  {MK,MK,4.5f,3.972135955f,3.623105626f,3.5f,3.623105626f,3.972135955f,4.5f,MK,MK},
  {MK,4.5f,3.742640687f,3.105551276f,2.662277660f,2.5f,2.662277660f,3.105551276f,3.742640687f,4.5f,MK},
  {4.885164807f,3.972135955f,3.105551276f,2.328427125f,1.736067977f,1.5f,1.736067977f,2.328427125f,3.105551276f,3.972135955f,4.885164807f},
  {4.599019514f,3.623105626f,2.662277660f,1.736067977f,0.914213562f,0.5f,0.914213562f,1.736067977f,2.662277660f,3.623105626f,4.599019514f},
  {4.5f,3.5f,2.5f,1.5f,0.5f,-0.5f,0.5f,1.5f,2.5f,3.5f,4.5f},
  {4.599019514f,3.623105626f,2.662277660f,1.736067977f,0.914213562f,0.5f,0.914213562f,1.736067977f,2.662277660f,3.623105626f,4.599019514f},
  {4.885164807f,3.972135955f,3.105551276f,2.328427125f,1.736067977f,1.5f,1.736067977f,2.328427125f,3.105551276f,3.972135955f,4.885164807f},
  {MK,4.5f,3.742640687f,3.105551276f,2.662277660f,2.5f,2.662277660f,3.105551276f,3.742640687f,4.5f,MK},
  {MK,MK,4.5f,3.972135955f,3.623105626f,3.5f,3.623105626f,3.972135955f,4.5f,MK,MK},
  {MK,MK,MK,4.885164807f,4.599019514f,4.5f,4.599019514f,4.885164807f,MK,MK,MK}
};

__global__ __launch_bounds__(256)
void scatter_render_kernel(const float* __restrict__ x,
                           const float* __restrict__ lens,
                           float* __restrict__ out)
{
    __shared__ __align__(16) float4 s4[HY][HX];   // (r, g, b, inv_es = e^{-4 disp})
    __shared__ float            sco[HY][HX];      // coc

    const int b   = blockIdx.z;
    const int gx0 = blockIdx.x * TX;
    const int gy0 = blockIdx.y * TY;

    const float scale = fabsf(lens[b]);
    const float* __restrict__ xb = x + (size_t)b * 4 * H * W;
    const float* __restrict__ pr = xb;
    const float* __restrict__ pg = xb + H * W;
    const float* __restrict__ pb = xb + 2 * H * W;
    const float* __restrict__ pd = xb + 3 * H * W;

    // ---- cooperative halo-tile fill (with edge clamp) ----
    const int tid = threadIdx.y * TX + threadIdx.x;
    for (int idx = tid; idx < HY * HX; idx += 256) {
        int yy = idx / HX;
        int xx = idx - yy * HX;
        int sy = gy0 + yy - 5; sy = min(max(sy, 0), H - 1);
        int sx = gx0 + xx - 5; sx = min(max(sx, 0), W - 1);
        int o  = sy * W + sx;
        float d  = pd[o];
        s4[yy][xx]  = make_float4(pr[o], pg[o], pb[o], __expf(-4.0f * d));
        sco[yy][xx] = scale * fabsf(d);
    }
    __syncthreads();

    // ---- main gather: each thread owns 2 vertically adjacent outputs ----
    const int tx = threadIdx.x;
    const int ry = 2 * threadIdx.y;

    // ed = e^{+4 disp_dst} = 1 / inv_es(dst)
    const float ed0 = __fdividef(1.0f, s4[ry + 5][tx + 5].w);
    const float ed1 = __fdividef(1.0f, s4[ry + 6][tx + 5].w);

    float nr0 = 0.f, ng0 = 0.f, nb0 = 0.f, nd0 = 0.f;
    float nr1 = 0.f, ng1 = 0.f, nb1 = 0.f, nd1 = 0.f;

    // smem row ry+sr serves out0 as disk row sr (sr=0..10) and out1 as disk
    // row sr-1 (sr=1..11). Only columns inside either disk span are touched.
    #pragma unroll
    for (int sr = 0; sr < 12; ++sr) {
        #pragma unroll
        for (int sc = 0; sc < 11; ++sc) {
            const bool a0 = (sr <= 10) && (sc >= ST[sr])     && (sc < ST[sr]     + WD[sr]);
            const bool a1 = (sr >= 1)  && (sc >= ST[sr - 1]) && (sc < ST[sr - 1] + WD[sr - 1]);
            if (a0 || a1) {
                const float4 f4 = s4[ry + sr][tx + sc];   // (r, g, b, inv_es)
                const float  cc = sco[ry + sr][tx + sc];  // coc
                if (a0) {
                    const float w  = __saturatef(cc - QD[sr][sc]);
                    // w * sigmoid(4(ds - dd)) = w / (1 + ed*inv_es)
                    const float wo = __fdividef(w, fmaf(ed0, f4.w, 1.0f));
                    nr0 += wo * f4.x;  ng0 += wo * f4.y;  nb0 += wo * f4.z;  nd0 += wo;
                }
                if (a1) {
                    const float w  = __saturatef(cc - QD[sr - 1][sc]);
                    const float wo = __fdividef(w, fmaf(ed1, f4.w, 1.0f));
                    nr1 += wo * f4.x;  ng1 += wo * f4.y;  nb1 += wo * f4.z;  nd1 += wo;
                }
            }
        }
    }

    const int gx = gx0 + tx;
    const int gy = gy0 + ry;
    float* __restrict__ ob = out + (size_t)b * 3 * H * W;
    const float inv0 = __fdividef(1.0f, nd0 + 1e-8f);
    const float inv1 = __fdividef(1.0f, nd1 + 1e-8f);
    const int o0 = gy * W + gx;
    const int o1 = o0 + W;
    ob[o0]             = nr0 * inv0;
    ob[H * W + o0]     = ng0 * inv0;
    ob[2 * H * W + o0] = nb0 * inv0;
    ob[o1]             = nr1 * inv1;
    ob[H * W + o1]     = ng1 * inv1;
    ob[2 * H * W + o1] = nb1 * inv1;
}

extern "C" void kernel_launch(void* const* d_in, const int* in_sizes, int n_in,
                              void* d_out, int out_size)
{
    const float* x    = (const float*)d_in[0];
    const float* lens = (const float*)d_in[1];
    float* out        = (float*)d_out;

    dim3 block(TX, TY / 2, 1);              // 32 x 8 = 256 threads
    dim3 grid(W / TX, H / TY, B);           // 32 x 64 x 4
    scatter_render_kernel<<<grid, block>>>(x, lens, out);
}